// round 15
// baseline (speedup 1.0000x reference)
#include <cuda_runtime.h>
#include <cuda_fp16.h>
#include <math.h>
#include <stdint.h>

#define BB 4
#define TT 2048
#define DD 1024
#define DK 128
#define RR (BB*TT)   // 8192

#define BKV 32
#define CHUNK 8             // KV tiles per flash block
#define BPB 72              // flash blocks per batch: sum_{q=0..15} ceil((4q+4)/8)
#define NSLOT (BB*BPB)      // 288 partial slots

// Scratch (device globals: allocation-free)
__device__ unsigned g_Qh[RR*(DK/2)];            // Q fp16 packed half2, pre-scaled
__device__ unsigned g_Kh[RR*(DK/2)];            // K fp16 packed half2
__device__ unsigned g_Vp[(RR/2)*DK];            // V fp16 TRANSPOSED: [b][d][t2]
__device__ unsigned g_Oh[RR*(DK/2)];            // attention O, fp16 packed half2
__device__ unsigned g_pOh[(size_t)NSLOT*128*(DK/2)]; // partial O, fp16 packed
__device__ float    g_pml[NSLOT*128*2];         // partial (m,l) per row
__device__ unsigned g_Wh[3*128*512];            // Wq/Wk/Wv packed [n][k2] (n-major)
__device__ unsigned g_WoH[1024*64];             // Wo packed [n][k2] (n-major)

// pack two f32 -> half2 u32 (lo = first arg, hi = second arg)
__device__ __forceinline__ unsigned f2h2(float lo, float hi) {
    unsigned u;
    asm("cvt.rn.f16x2.f32 %0, %1, %2;" : "=r"(u) : "f"(hi), "f"(lo));
    return u;
}

__device__ __forceinline__ float2 h2f2(unsigned u) {
    __half2 h = *(__half2*)&u;
    return __half22float2(h);
}

__device__ __forceinline__ void mma_f16(float c[4],
    unsigned a0, unsigned a1, unsigned a2, unsigned a3,
    unsigned b0, unsigned b1)
{
    asm volatile(
        "mma.sync.aligned.m16n8k16.row.col.f32.f16.f16.f32 "
        "{%0,%1,%2,%3}, {%4,%5,%6,%7}, {%8,%9}, {%0,%1,%2,%3};"
        : "+f"(c[0]), "+f"(c[1]), "+f"(c[2]), "+f"(c[3])
        : "r"(a0), "r"(a1), "r"(a2), "r"(a3), "r"(b0), "r"(b1));
}

__device__ __forceinline__ void ldmx4(unsigned* r, uint32_t addr) {
    asm volatile("ldmatrix.sync.aligned.m8n8.x4.shared.b16 {%0,%1,%2,%3}, [%4];"
        : "=r"(r[0]), "=r"(r[1]), "=r"(r[2]), "=r"(r[3]) : "r"(addr));
}

__device__ __forceinline__ uint32_t smem_u32(const void* p) {
    uint32_t a;
    asm("{ .reg .u64 t; cvta.to.shared.u64 t, %1; cvt.u32.u64 %0, t; }"
        : "=r"(a) : "l"(p));
    return a;
}

__device__ __forceinline__ void cp16(uint32_t dst, const void* src) {
    asm volatile("cp.async.ca.shared.global [%0], [%1], 16;"
                 :: "r"(dst), "l"(src) : "memory");
}
#define CP_COMMIT() asm volatile("cp.async.commit_group;" ::: "memory")
#define CP_WAIT0()  asm volatile("cp.async.wait_group 0;"  ::: "memory")

// ---------------------------------------------------------------------------
// Pack weights into n-major fp16 k-pair layouts (smem-tiled transpose):
// g_Wh[w][n*512 + k2]  = half2(W[2k2][n], W[2k2+1][n])  (Wq/Wk/Wv, K=1024,N=128)
// g_WoH[n*64 + k2]     = same for Wo (K=128, N=1024).   Grid 256 x (32,8).
// ---------------------------------------------------------------------------
__global__ __launch_bounds__(256) void packw_kernel(
    const float* __restrict__ Wq, const float* __restrict__ Wk,
    const float* __restrict__ Wv, const float* __restrict__ Wo)
{
    __shared__ unsigned t[32][33];
    const int bid = blockIdx.x;
    const int tx = threadIdx.x & 31, ty = threadIdx.x >> 5;

    if (bid < 192) {
        const int wsel = bid >> 6, tt = bid & 63;
        const int tk = tt & 15, tn = tt >> 4;     // k2-tile 0..15, n-tile 0..3
        const float* W = (wsel == 0) ? Wq : (wsel == 1) ? Wk : Wv;
#pragma unroll
        for (int i = 0; i < 4; i++) {
            int k2 = tk * 32 + ty + 8 * i;
            int n  = tn * 32 + tx;
            t[ty + 8 * i][tx] = f2h2(W[(2 * k2) * 128 + n], W[(2 * k2 + 1) * 128 + n]);
        }
        __syncthreads();
        unsigned* dst = g_Wh + wsel * 65536;
#pragma unroll
        for (int i = 0; i < 4; i++)
            dst[(tn * 32 + ty + 8 * i) * 512 + tk * 32 + tx] = t[tx][ty + 8 * i];
    } else {
        const int tt = bid - 192;
        const int tk = tt & 1, tn = tt >> 1;      // k2-tile 0..1, n-tile 0..31
#pragma unroll
        for (int i = 0; i < 4; i++) {
            int k2 = tk * 32 + ty + 8 * i;
            int n  = tn * 32 + tx;
            t[ty + 8 * i][tx] = f2h2(Wo[(2 * k2) * 1024 + n], Wo[(2 * k2 + 1) * 1024 + n]);
        }
        __syncthreads();
#pragma unroll
        for (int i = 0; i < 4; i++)
            g_WoH[(tn * 32 + ty + 8 * i) * 64 + tk * 32 + tx] = t[tx][ty + 8 * i];
    }
}

// ---------------------------------------------------------------------------
// QKV GEMM: C[128x128 tile] = x[M,1024] @ W[1024,128]. A = fp32 x (cvt at
// staging, register prefetch); B = n-major packed weights via cp.async,
// fragments via ldmatrix.x4. mode 1 = half2 Ch out; mode 2 = V transposed
// pack to g_Vp. 8 warps as 2(m) x 4(n); warp tile 64x32; BK=32.
// As: [m][k2] stride 20. Bs: [n][k2] stride 20 (both ldmatrix-safe).
// ---------------------------------------------------------------------------
#define AST 20
#define BST2 20

__device__ __forceinline__ void qkv_gemm(
    const float* __restrict__ A, const unsigned* __restrict__ Bh,
    unsigned* __restrict__ Ch, float oscale, int mode, int m0)
{
    __shared__ __align__(16) unsigned As[2 * 128 * AST];
    __shared__ __align__(16) unsigned Bs[2 * 128 * BST2];

    const int tid = threadIdx.x, lane = tid & 31, w = tid >> 5;
    const int wm = (w >> 2) * 64, wn = (w & 3) * 32;
    const int g = lane >> 2, c = lane & 3;
    const uint32_t as_base = smem_u32(As);
    const uint32_t bs_base = smem_u32(Bs);
    // ldmatrix B lane mapping: matrix = lane>>3, row-in-matrix = lane&7
    const int lm_p = (lane >> 4) & 1;       // nf-pair member
    const int lm_h = (lane >> 3) & 1;       // k-half
    const int lm_r = lane & 7;
    const uint32_t b_lm_off = 4u * ((wn + lm_p * 8 + lm_r) * BST2 + lm_h * 4);

    float acc[4][4][4];
#pragma unroll
    for (int mf = 0; mf < 4; mf++)
#pragma unroll
        for (int nf = 0; nf < 4; nf++)
#pragma unroll
            for (int j = 0; j < 4; j++) acc[mf][nf][j] = 0.f;

    const int arow = tid >> 1;
    const int aku  = (tid & 1) * 8;
    const int brow = tid >> 1, bpart = tid & 1;

    auto stageB = [&](int k0, int s) {
        uint32_t dst = bs_base + 4u * (s * 128 * BST2 + brow * BST2 + bpart * 8);
        const unsigned* src = &Bh[brow * 512 + k0 / 2 + bpart * 8];
        cp16(dst, src);
        cp16(dst + 16, src + 4);
    };

    stageB(0, 0);
    CP_COMMIT();
    float4 av[4];
#pragma unroll
    for (int i = 0; i < 4; i++)
        av[i] = *(const float4*)&A[(size_t)(m0 + arow) * DD + aku * 2 + i * 4];

    int s = 0;
    for (int k0 = 0; k0 < DD; k0 += 32) {
        unsigned* Ab = As + s * 128 * AST;
        {
            uint4 u0 = {f2h2(av[0].x, av[0].y), f2h2(av[0].z, av[0].w),
                        f2h2(av[1].x, av[1].y), f2h2(av[1].z, av[1].w)};
            uint4 u1 = {f2h2(av[2].x, av[2].y), f2h2(av[2].z, av[2].w),
                        f2h2(av[3].x, av[3].y), f2h2(av[3].z, av[3].w)};
            *(uint4*)&Ab[arow * AST + aku]     = u0;
            *(uint4*)&Ab[arow * AST + aku + 4] = u1;
        }
        CP_WAIT0();
        __syncthreads();

        if (k0 + 32 < DD) {
#pragma unroll
            for (int i = 0; i < 4; i++)
                av[i] = *(const float4*)&A[(size_t)(m0 + arow) * DD + k0 + 32 + aku * 2 + i * 4];
            stageB(k0 + 32, s ^ 1);
            CP_COMMIT();
        }

        const uint32_t abase_s = as_base + 4u * (s * 128 * AST);
        const uint32_t bbase_s = bs_base + 4u * (s * 128 * BST2) + b_lm_off;
#pragma unroll
        for (int ks = 0; ks < 2; ks++) {
            unsigned a[4][4];
#pragma unroll
            for (int mf = 0; mf < 4; mf++)
                ldmx4(a[mf], abase_s +
                      4u * ((wm + mf * 16 + (lane & 15)) * AST + ks * 8 + (lane >> 4) * 4));
#pragma unroll
            for (int j = 0; j < 2; j++) {
                unsigned bk[4];
                ldmx4(bk, bbase_s + j * (16 * BST2 * 4) + ks * 32);
#pragma unroll
                for (int mf = 0; mf < 4; mf++) {
                    mma_f16(acc[mf][2*j],   a[mf][0], a[mf][1], a[mf][2], a[mf][3],
                            bk[0], bk[1]);
                    mma_f16(acc[mf][2*j+1], a[mf][0], a[mf][1], a[mf][2], a[mf][3],
                            bk[2], bk[3]);
                }
            }
        }
        s ^= 1;
    }

    if (mode == 1) {
#pragma unroll
        for (int mf = 0; mf < 4; mf++)
#pragma unroll
            for (int nf = 0; nf < 4; nf++) {
                int row  = m0 + wm + mf * 16 + g;
                int col2 = (wn + nf * 8) / 2 + c;
                Ch[(size_t)row * 64 + col2] =
                    f2h2(acc[mf][nf][0] * oscale, acc[mf][nf][1] * oscale);
                Ch[(size_t)(row + 8) * 64 + col2] =
                    f2h2(acc[mf][nf][2] * oscale, acc[mf][nf][3] * oscale);
            }
    } else {
        // V transposed pack: g_Vp[(b*128 + d) * 1024 + t2] = half2(tok even, tok odd)
#pragma unroll
        for (int mf = 0; mf < 4; mf++)
#pragma unroll
            for (int nf = 0; nf < 4; nf++) {
                float p0 = __shfl_xor_sync(0xffffffffu, acc[mf][nf][0], 4);
                float p1 = __shfl_xor_sync(0xffffffffu, acc[mf][nf][1], 4);
                float p2 = __shfl_xor_sync(0xffffffffu, acc[mf][nf][2], 4);
                float p3 = __shfl_xor_sync(0xffffffffu, acc[mf][nf][3], 4);
                if (!(g & 1)) {
                    int r0  = m0 + wm + mf * 16 + g;       // even token
                    int bb  = r0 >> 11;
                    int t2a = (r0 & 2047) >> 1;
                    int col = wn + nf * 8 + 2 * c;
                    g_Vp[((size_t)(bb * 128 + col))     * 1024 + t2a]     = f2h2(acc[mf][nf][0], p0);
                    g_Vp[((size_t)(bb * 128 + col + 1)) * 1024 + t2a]     = f2h2(acc[mf][nf][1], p1);
                    g_Vp[((size_t)(bb * 128 + col))     * 1024 + t2a + 4] = f2h2(acc[mf][nf][2], p2);
                    g_Vp[((size_t)(bb * 128 + col + 1)) * 1024 + t2a + 4] = f2h2(acc[mf][nf][3], p3);
                }
            }
    }
}

__global__ __launch_bounds__(256) void qkv_kernel(const float* __restrict__ x)
{
    const float scale = 0.08838834764831845f;   // 1/sqrt(128), folded into Q
    const unsigned* Bh = g_Wh + blockIdx.z * 65536;
    if (blockIdx.z == 0)
        qkv_gemm(x, Bh, g_Qh, scale, 1, blockIdx.x * 128);
    else if (blockIdx.z == 1)
        qkv_gemm(x, Bh, g_Kh, 1.0f, 1, blockIdx.x * 128);
    else
        qkv_gemm(x, Bh, nullptr, 1.0f, 2, blockIdx.x * 128);
}

// ---------------------------------------------------------------------------
// Output projection: out[128x128 tile] = O[8192,128] @ Wo[128,1024].
// One-shot cp.async stage (A fp16 g_Oh [m][k2] str 68; B g_WoH [n][k2] str 68),
// ONE barrier, 8 k16-slices, A+B fragments all via ldmatrix.x4.
// ---------------------------------------------------------------------------
#define OA_ST 68
#define OB_ST 68
#define OP_SMEM ((128*OA_ST + 128*OB_ST) * 4)   // 69,632 bytes

__global__ __launch_bounds__(256) void outproj_kernel(float* __restrict__ out)
{
    extern __shared__ __align__(16) unsigned sop[];

    const int tid = threadIdx.x, lane = tid & 31, w = tid >> 5;
    const int wm = (w >> 2) * 64, wn = (w & 3) * 32;
    const int g = lane >> 2, c = lane & 3;
    const int m0 = blockIdx.y * 128, n0 = blockIdx.x * 128;
    const uint32_t sb = smem_u32(sop);
    const int lm_p = (lane >> 4) & 1;
    const int lm_h = (lane >> 3) & 1;
    const int lm_r = lane & 7;

    // stage A: 128 rows x 64 u32
    {
        const int row = tid >> 1, half = tid & 1;
        const unsigned* src = &g_Oh[(size_t)(m0 + row) * 64 + half * 32];
        uint32_t dst = sb + 4u * (row * OA_ST + half * 32);
#pragma unroll
        for (int i = 0; i < 8; i++)
            cp16(dst + i * 16, src + i * 4);
    }
    // stage B: 128 n-rows x 64 u32
    {
        const int row = tid >> 1, half = tid & 1;
        const unsigned* src = &g_WoH[(size_t)(n0 + row) * 64 + half * 32];
        uint32_t dst = sb + 4u * (128 * OA_ST + row * OB_ST + half * 32);
#pragma unroll
        for (int i = 0; i < 8; i++)
            cp16(dst + i * 16, src + i * 4);
    }
    CP_COMMIT();
    CP_WAIT0();
    __syncthreads();

    float acc[4][4][4];
#pragma unroll
    for (int mf = 0; mf < 4; mf++)
#pragma unroll
        for (int nf = 0; nf < 4; nf++)
#pragma unroll
            for (int j = 0; j < 4; j++) acc[mf][nf][j] = 0.f;

    const uint32_t a_lm = sb + 4u * ((wm + (lane & 15)) * OA_ST + (lane >> 4) * 4);
    const uint32_t b_lm = sb + 4u * (128 * OA_ST + (wn + lm_p * 8 + lm_r) * OB_ST + lm_h * 4);
#pragma unroll
    for (int ks = 0; ks < 8; ks++) {
        unsigned a[4][4];
#pragma unroll
        for (int mf = 0; mf < 4; mf++)
            ldmx4(a[mf], a_lm + 4u * (mf * 16 * OA_ST) + ks * 32);
#pragma unroll
        for (int j = 0; j < 2; j++) {
            unsigned bk[4];
            ldmx4(bk, b_lm + j * (16 * OB_ST * 4) + ks * 32);
#pragma unroll
            for (int mf = 0; mf < 4; mf++) {
                mma_f16(acc[mf][2*j],   a[mf][0], a[mf][1], a[mf][2], a[mf][3],
                        bk[0], bk[1]);
                mma_f16(acc[mf][2*j+1], a[mf][0], a[mf][1], a[mf][2], a[mf][3],
                        bk[2], bk[3]);
            }
        }
    }

#pragma unroll
    for (int mf = 0; mf < 4; mf++)
#pragma unroll
        for (int nf = 0; nf < 4; nf++) {
            size_t r0 = (size_t)(m0 + wm + mf * 16 + g) * DD + n0 + wn + nf * 8 + 2 * c;
            float2 lo = {acc[mf][nf][0], acc[mf][nf][1]};
            float2 hi = {acc[mf][nf][2], acc[mf][nf][3]};
            *(float2*)&out[r0]                  = lo;
            *(float2*)&out[r0 + (size_t)8 * DD] = hi;
        }
}

// ---------------------------------------------------------------------------
// Flash attention, fp16 mma, split-KV, cp.async staging, ldmatrix for ALL
// operand fragments. BQ=128, BKV=32, 8 warps, chunk=8, 288 blocks, 2/SM.
// Qs [m][d2] str 68; Ks [key][d2] str 68; Vs TRANSPOSED [d][k2] str 20.
// ---------------------------------------------------------------------------
#define QS2 68
#define KS2 68
#define VST2 20
#define OFF_K (128*QS2)
#define OFF_V (OFF_K + 2*BKV*KS2)
#define FLASH_SMEM ((OFF_V + 2*128*VST2) * 4)   // 72,704 bytes

__global__ __launch_bounds__(256, 2) void flash_kernel()
{
    extern __shared__ __align__(16) unsigned smf[];

    const int tid = threadIdx.x, lane = tid & 31, w = tid >> 5;
    const int g = lane >> 2, c = lane & 3;
    const int wm = w * 16;
    const uint32_t sbase = smem_u32(smf);
    const uint32_t qs_lm = sbase +
        4u * ((wm + (lane & 15)) * QS2 + (lane >> 4) * 4);
    const int lm_p = (lane >> 4) & 1;
    const int lm_h = (lane >> 3) & 1;
    const int lm_r = lane & 7;
    const uint32_t k_lm_off = 4u * ((lm_p * 8 + lm_r) * KS2 + lm_h * 4);
    const uint32_t v_lm_off = 4u * ((lm_p * 8 + lm_r) * VST2 + lm_h * 4);

    const int b  = blockIdx.x / BPB;
    const int wr = BPB - 1 - (blockIdx.x % BPB);
    int qt = 0, chunk = 0, prefix = 0;
    {
        int accn = 0;
        for (int q = 0; q < 16; q++) {
            int n = (q + 2) >> 1;
            if (wr < accn + n) { qt = q; chunk = wr - accn; prefix = accn; break; }
            accn += n;
        }
    }
    const int slot = b * BPB + prefix + chunk;
    const int q0 = qt * 128;
    const int it_total = 4 * qt + 4;
    const int t0 = chunk * CHUNK;
    const int tlen = (it_total - t0 < CHUNK) ? (it_total - t0) : CHUNK;

    const size_t bT = (size_t)b * TT;

    const int kr = tid >> 3,  kku = (tid & 7) * 8;   // K: key row, u32 group
    const int vr = tid >> 1,  vpart = tid & 1;       // V: d row, half
    const int qr = tid >> 1,  qku = (tid & 1) * 32;  // Q: row, u32 group

    auto stage = [&](int t, int s) {
        uint32_t kb = sbase + (OFF_K + s * BKV * KS2 + kr * KS2 + kku) * 4;
        const unsigned* ksrc = &g_Kh[(bT + (size_t)t * BKV + kr) * 64 + kku];
        cp16(kb,      ksrc);
        cp16(kb + 16, ksrc + 4);
        uint32_t vb = sbase + (OFF_V + s * 128 * VST2 + vr * VST2 + vpart * 8) * 4;
        const unsigned* vsrc = &g_Vp[((size_t)(b * 128 + vr)) * 1024 + t * 16 + vpart * 8];
        cp16(vb,      vsrc);
        cp16(vb + 16, vsrc + 4);
    };

    {
        const unsigned* qsrc = &g_Qh[(bT + q0 + qr) * 64 + qku];
        uint32_t qb = sbase + (qr * QS2 + qku) * 4;
#pragma unroll
        for (int i = 0; i < 8; i++)
            cp16(qb + i * 16, qsrc + i * 4);
        stage(t0, 0);
        CP_COMMIT();
        CP_WAIT0();
        __syncthreads();
    }

    float mr0 = -1e30f, mr1 = -1e30f, l0 = 0.f, l1 = 0.f;
    float O[16][4];
#pragma unroll
    for (int nf = 0; nf < 16; nf++)
#pragma unroll
        for (int j = 0; j < 4; j++) O[nf][j] = 0.f;

    int s = 0;
    for (int ti = 0; ti < tlen; ti++) {
        const int t = t0 + ti;
        const uint32_t kfb = sbase + 4u * (OFF_K + s * BKV * KS2) + k_lm_off;
        const uint32_t vfb = sbase + 4u * (OFF_V + s * 128 * VST2) + v_lm_off;

        if (ti + 1 < tlen) { stage(t + 1, s ^ 1); CP_COMMIT(); }

        // --- S = Q K^T : 4 n-frags, 8 k16-slices; K frags via ldmatrix ---
        float sfr[4][4];
#pragma unroll
        for (int nf = 0; nf < 4; nf++)
#pragma unroll
            for (int j = 0; j < 4; j++) sfr[nf][j] = 0.f;

#pragma unroll
        for (int ks = 0; ks < 8; ks++) {
            unsigned aq[4];
            ldmx4(aq, qs_lm + ks * 32);
#pragma unroll
            for (int j = 0; j < 2; j++) {
                unsigned bk[4];
                ldmx4(bk, kfb + j * (16 * KS2 * 4) + ks * 32);
                mma_f16(sfr[2*j],   aq[0], aq[1], aq[2], aq[3], bk[0], bk[1]);
                mma_f16(sfr[2*j+1], aq[0], aq[1], aq[2], aq[3], bk[2], bk[3]);
            }
        }

        // causal mask (scale pre-folded into Q)
        if (t * BKV + BKV - 1 > q0 + wm) {
            const int r0g = q0 + wm + g, r1g = r0g + 8;
#pragma unroll
            for (int nf = 0; nf < 4; nf++) {
                int col = t * BKV + nf * 8 + 2 * c;
                if (col     > r0g) sfr[nf][0] = -1e30f;
                if (col + 1 > r0g) sfr[nf][1] = -1e30f;
                if (col     > r1g) sfr[nf][2] = -1e30f;
                if (col + 1 > r1g) sfr[nf][3] = -1e30f;
            }
        }

        // --- online softmax ---
        float rm0 = -1e30f, rm1 = -1e30f;
#pragma unroll
        for (int nf = 0; nf < 4; nf++) {
            rm0 = fmaxf(rm0, fmaxf(sfr[nf][0], sfr[nf][1]));
            rm1 = fmaxf(rm1, fmaxf(sfr[nf][2], sfr[nf][3]));
        }
        rm0 = fmaxf(rm0, __shfl_xor_sync(0xffffffffu, rm0, 1));
        rm0 = fmaxf(rm0, __shfl_xor_sync(0xffffffffu, rm0, 2));
        rm1 = fmaxf(rm1, __shfl_xor_sync(0xffffffffu, rm1, 1));
        rm1 = fmaxf(rm1, __shfl_xor_sync(0xffffffffu, rm1, 2));

        float mn0 = fmaxf(mr0, rm0), mn1 = fmaxf(mr1, rm1);
        float al0 = __expf(mr0 - mn0), al1 = __expf(mr1 - mn1);
        float sum0 = 0.f, sum1 = 0.f;
#pragma unroll
        for (int nf = 0; nf < 4; nf++) {
            sfr[nf][0] = __expf(sfr[nf][0] - mn0);
            sfr[nf][1] = __expf(sfr[nf][1] - mn0);
            sfr[nf][2] = __expf(sfr[nf][2] - mn1);
            sfr[nf][3] = __expf(sfr[nf][3] - mn1);
            sum0 += sfr[nf][0] + sfr[nf][1];
            sum1 += sfr[nf][2] + sfr[nf][3];
        }
        sum0 += __shfl_xor_sync(0xffffffffu, sum0, 1);
        sum0 += __shfl_xor_sync(0xffffffffu, sum0, 2);
        sum1 += __shfl_xor_sync(0xffffffffu, sum1, 1);
        sum1 += __shfl_xor_sync(0xffffffffu, sum1, 2);

        l0 = l0 * al0 + sum0; l1 = l1 * al1 + sum1;
        mr0 = mn0; mr1 = mn1;
#pragma unroll
        for (int nf = 0; nf < 16; nf++) {
            O[nf][0] *= al0; O[nf][1] *= al0;
            O[nf][2] *= al1; O[nf][3] *= al1;
        }

        // --- O += P V : V frags via ldmatrix (transposed layout) ---
#pragma unroll
        for (int ksl = 0; ksl < 2; ksl++) {
            unsigned a0 = f2h2(sfr[2 * ksl][0],     sfr[2 * ksl][1]);
            unsigned a1 = f2h2(sfr[2 * ksl][2],     sfr[2 * ksl][3]);
            unsigned a2 = f2h2(sfr[2 * ksl + 1][0], sfr[2 * ksl + 1][1]);
            unsigned a3 = f2h2(sfr[2 * ksl + 1][2], sfr[2 * ksl + 1][3]);
#pragma unroll
            for (int j = 0; j < 8; j++) {
                unsigned bv[4];
                ldmx4(bv, vfb + j * (16 * VST2 * 4) + ksl * 32);
                mma_f16(O[2*j],   a0, a1, a2, a3, bv[0], bv[1]);
                mma_f16(O[2*j+1], a0, a1, a2, a3, bv[2], bv[3]);
            }
        }

        if (ti + 1 < tlen) CP_WAIT0();
        __syncthreads();
        s ^= 1;
    }

    unsigned* pO = g_pOh + (size_t)slot * 128 * 64;
#pragma unroll
    for (int nf = 0; nf < 16; nf++) {
        int col2 = nf * 4 + c;
        pO[(wm + g) * 64 + col2]     = f2h2(O[nf][0], O[nf][1]);
        pO[(wm + g + 8) * 64 + col2] = f2h2(O[nf][2], O[nf][3]);
    }
    if (c == 0) {
        float* ml = g_pml + slot * 256;
        ml[(wm + g) * 2]         = mr0;
        ml[(wm + g) * 2 + 1]     = l0;
        ml[(wm + g + 8) * 2]     = mr1;
        ml[(wm + g + 8) * 2 + 1] = l1;
    }
}

// ---------------------------------------------------------------------------
// Combine partial chunks -> g_Oh (normalized, packed fp16). 1024 blocks.
// ---------------------------------------------------------------------------
__global__ __launch_bounds__(256) void combine_kernel()
{
    const int idx  = blockIdx.x * 256 + threadIdx.x;
    const int col2 = (idx & 31) * 2;
    const int row  = (idx >> 5) & 127;
    const int bqt  = idx >> 12;
    const int b = bqt >> 4, qt = bqt & 15;
    const int nch = (qt + 2) >> 1;
    int prefix = 0;
#pragma unroll
    for (int q = 0; q < 16; q++)
        if (q < qt) prefix += (q + 2) >> 1;
    const int base = b * BPB + prefix;

    float M = -1e30f;
    for (int i = 0; i < nch; i++)
        M = fmaxf(M, g_pml[(base + i) * 256 + row * 2]);

    float L = 0.f;
    float4 a = {0.f, 0.f, 0.f, 0.f};
    for (int i = 0; i < nch; i++) {
        float mi = g_pml[(base + i) * 256 + row * 2];
        float li = g_pml[(base + i) * 256 + row * 2 + 1];
        float wgt = __expf(mi - M);
        L += wgt * li;
        uint2 v = *(const uint2*)&g_pOh[((size_t)(base + i) * 128 + row) * 64 + col2];
        float2 lo = h2f2(v.x), hi = h2f2(v.y);
        a.x += wgt * lo.x; a.y += wgt * lo.y;
        a.z += wgt * hi.x; a.w += wgt * hi.y;
    }
    const float invL = 1.f / L;
    const size_t orow = (size_t)b * TT + qt * 128 + row;
    g_Oh[orow * 64 + col2]     = f2h2(a.x * invL, a.y * invL);
    g_Oh[orow * 64 + col2 + 1] = f2h2(a.z * invL, a.w * invL);
}

// ---------------------------------------------------------------------------
extern "C" void kernel_launch(void* const* d_in, const int* in_sizes, int n_in,
                              void* d_out, int out_size)
{
    const float* x  = (const float*)d_in[0];
    const float* Wq = (const float*)d_in[1];
    const float* Wk = (const float*)d_in[2];
    const float* Wv = (const float*)d_in[3];
    const float* Wo = (const float*)d_in[4];
    float* out = (float*)d_out;

    cudaFuncSetAttribute(flash_kernel,
                         cudaFuncAttributeMaxDynamicSharedMemorySize, FLASH_SMEM);
    cudaFuncSetAttribute(outproj_kernel,
                         cudaFuncAttributeMaxDynamicSharedMemorySize, OP_SMEM);

    // Pack all weights into n-major fp16 k-pair layout (tiled transpose)
    packw_kernel<<<256, dim3(256)>>>(Wq, Wk, Wv, Wo);

    // QKV projections: A = fp32 x (cvt), B = packed weights, ldmatrix frags
    qkv_kernel<<<dim3(RR / 128, 1, 3), 256>>>(x);

    // Split-KV causal flash attention (288 blocks = full wave at 2/SM)
    flash_kernel<<<NSLOT, 256, FLASH_SMEM>>>();

    // Merge partial softmax chunks -> packed fp16 O
    combine_kernel<<<RR * 32 / 256, 256>>>();

    // Output projection: one-shot smem, ldmatrix everywhere
    outproj_kernel<<<dim3(DD / 128, RR / 128), 256, OP_SMEM>>>(out);
}

// round 16
// speedup vs baseline: 1.0224x; 1.0224x over previous
#include <cuda_runtime.h>
#include <cuda_fp16.h>
#include <math.h>
#include <stdint.h>

#define BB 4
#define TT 2048
#define DD 1024
#define DK 128
#define RR (BB*TT)   // 8192

#define BKV 32
#define CHUNK 8             // KV tiles per flash block
#define BPB 72              // flash blocks per batch: sum_{q=0..15} ceil((4q+4)/8)
#define NSLOT (BB*BPB)      // 288 partial slots

// Scratch (device globals: allocation-free)
__device__ unsigned g_Qh[RR*(DK/2)];            // Q fp16 packed half2, pre-scaled (log2e folded)
__device__ unsigned g_Kh[RR*(DK/2)];            // K fp16 packed half2
__device__ unsigned g_Vp[(RR/2)*DK];            // V fp16, key-pair packed: [t2][d]
__device__ unsigned g_Oh[RR*(DK/2)];            // attention O, fp16 packed half2
__device__ unsigned g_pOh[(size_t)NSLOT*128*(DK/2)]; // partial O, fp16 packed
__device__ float    g_pml[NSLOT*128*2];         // partial (m,l) per row (m in log2 units)
__device__ unsigned g_Wh[3*512*128];            // Wq/Wk/Wv packed k-pair: [k2][n]
__device__ unsigned g_WoH[64*1024];             // Wo packed k-pair: [k2][n]

// pack two f32 -> half2 u32 (lo = first arg, hi = second arg)
__device__ __forceinline__ unsigned f2h2(float lo, float hi) {
    unsigned u;
    asm("cvt.rn.f16x2.f32 %0, %1, %2;" : "=r"(u) : "f"(hi), "f"(lo));
    return u;
}

__device__ __forceinline__ float2 h2f2(unsigned u) {
    __half2 h = *(__half2*)&u;
    return __half22float2(h);
}

__device__ __forceinline__ void mma_f16(float c[4],
    unsigned a0, unsigned a1, unsigned a2, unsigned a3,
    unsigned b0, unsigned b1)
{
    asm volatile(
        "mma.sync.aligned.m16n8k16.row.col.f32.f16.f16.f32 "
        "{%0,%1,%2,%3}, {%4,%5,%6,%7}, {%8,%9}, {%0,%1,%2,%3};"
        : "+f"(c[0]), "+f"(c[1]), "+f"(c[2]), "+f"(c[3])
        : "r"(a0), "r"(a1), "r"(a2), "r"(a3), "r"(b0), "r"(b1));
}

__device__ __forceinline__ void ldmx4(unsigned* r, uint32_t addr) {
    asm volatile("ldmatrix.sync.aligned.m8n8.x4.shared.b16 {%0,%1,%2,%3}, [%4];"
        : "=r"(r[0]), "=r"(r[1]), "=r"(r[2]), "=r"(r[3]) : "r"(addr));
}

__device__ __forceinline__ uint32_t smem_u32(const void* p) {
    uint32_t a;
    asm("{ .reg .u64 t; cvta.to.shared.u64 t, %1; cvt.u32.u64 %0, t; }"
        : "=r"(a) : "l"(p));
    return a;
}

__device__ __forceinline__ void cp16(uint32_t dst, const void* src) {
    asm volatile("cp.async.ca.shared.global [%0], [%1], 16;"
                 :: "r"(dst), "l"(src) : "memory");
}
#define CP_COMMIT() asm volatile("cp.async.commit_group;" ::: "memory")
#define CP_WAIT0()  asm volatile("cp.async.wait_group 0;"  ::: "memory")

// ---------------------------------------------------------------------------
// Pack weights into fp16 k-pair layouts (matches GEMM B smem layout):
// g_Wh[w][k2*128+n] = half2(W[2k2][n], W[2k2+1][n]) for Wq/Wk/Wv (K=1024,N=128)
// g_WoH[k2*1024+n]  = same for Wo (K=128, N=1024).  Grid: 1024 x 256.
// ---------------------------------------------------------------------------
__global__ __launch_bounds__(256) void packw_kernel(
    const float* __restrict__ Wq, const float* __restrict__ Wk,
    const float* __restrict__ Wv, const float* __restrict__ Wo)
{
    const int idx = blockIdx.x * 256 + threadIdx.x;
    if (idx < 3 * 65536) {
        const int wsel = idx >> 16;
        const int r = idx & 65535;
        const int k2 = r >> 7, n = r & 127;
        const float* W = (wsel == 0) ? Wq : (wsel == 1) ? Wk : Wv;
        g_Wh[idx] = f2h2(W[(2 * k2) * 128 + n], W[(2 * k2 + 1) * 128 + n]);
    } else {
        const int r = idx - 3 * 65536;
        const int k2 = r >> 10, n = r & 1023;
        g_WoH[r] = f2h2(Wo[(2 * k2) * 1024 + n], Wo[(2 * k2 + 1) * 1024 + n]);
    }
}

// ---------------------------------------------------------------------------
// QKV GEMM: C[128x128 tile] = x[M,1024] @ W[1024,128]. A = fp32 x (cvt at
// staging, register prefetch); B = pre-packed fp16 weights via cp.async.
// mode: 1 = half2 Ch out (oscale folded), 2 = V key-pair packed out to g_Vp.
// 256 threads = 8 warps as 2(m) x 4(n); warp tile 64x32; BK=32.
// As: [m][k2] packed half2, stride 20 u32 (ldmatrix). Bs: [k2][n] stride 136.
// ---------------------------------------------------------------------------
#define AST 20
#define BST 136

__device__ __forceinline__ void qkv_gemm(
    const float* __restrict__ A, const unsigned* __restrict__ Bh,
    unsigned* __restrict__ Ch, float oscale, int mode, int m0)
{
    __shared__ __align__(16) unsigned As[2 * 128 * AST];
    __shared__ __align__(16) unsigned Bs[2 * 16 * BST];

    const int tid = threadIdx.x, lane = tid & 31, w = tid >> 5;
    const int wm = (w >> 2) * 64, wn = (w & 3) * 32;
    const int g = lane >> 2, c = lane & 3;
    const uint32_t as_base = smem_u32(As);
    const uint32_t bs_base = smem_u32(Bs);

    float acc[4][4][4];
#pragma unroll
    for (int mf = 0; mf < 4; mf++)
#pragma unroll
        for (int nf = 0; nf < 4; nf++)
#pragma unroll
            for (int j = 0; j < 4; j++) acc[mf][nf][j] = 0.f;

    const int arow = tid >> 1;
    const int aku  = (tid & 1) * 8;
    const int bk2  = tid >> 4;            // 0..15
    const int bn0  = (tid & 15) * 8;

    auto stageB = [&](int k0, int s) {
        uint32_t dst = bs_base + 4u * (s * 16 * BST + bk2 * BST + bn0);
        const unsigned* src = &Bh[(k0 / 2 + bk2) * 128 + bn0];
        cp16(dst, src);
        cp16(dst + 16, src + 4);
    };

    stageB(0, 0);
    CP_COMMIT();
    float4 av[4];
#pragma unroll
    for (int i = 0; i < 4; i++)
        av[i] = *(const float4*)&A[(size_t)(m0 + arow) * DD + aku * 2 + i * 4];

    int s = 0;
    for (int k0 = 0; k0 < DD; k0 += 32) {
        unsigned* Ab = As + s * 128 * AST;
        {
            uint4 u0 = {f2h2(av[0].x, av[0].y), f2h2(av[0].z, av[0].w),
                        f2h2(av[1].x, av[1].y), f2h2(av[1].z, av[1].w)};
            uint4 u1 = {f2h2(av[2].x, av[2].y), f2h2(av[2].z, av[2].w),
                        f2h2(av[3].x, av[3].y), f2h2(av[3].z, av[3].w)};
            *(uint4*)&Ab[arow * AST + aku]     = u0;
            *(uint4*)&Ab[arow * AST + aku + 4] = u1;
        }
        CP_WAIT0();
        __syncthreads();

        if (k0 + 32 < DD) {
#pragma unroll
            for (int i = 0; i < 4; i++)
                av[i] = *(const float4*)&A[(size_t)(m0 + arow) * DD + k0 + 32 + aku * 2 + i * 4];
            stageB(k0 + 32, s ^ 1);
            CP_COMMIT();
        }

        unsigned* Bb = Bs + s * 16 * BST;
        const uint32_t abase_s = as_base + 4u * (s * 128 * AST);
#pragma unroll
        for (int ks = 0; ks < 2; ks++) {
            const int kk = ks * 8 + c;
            unsigned a[4][4], b[4][2];
#pragma unroll
            for (int mf = 0; mf < 4; mf++)
                ldmx4(a[mf], abase_s +
                      4u * ((wm + mf * 16 + (lane & 15)) * AST + ks * 8 + (lane >> 4) * 4));
#pragma unroll
            for (int nf = 0; nf < 4; nf++) {
                int n = wn + nf * 8 + g;
                b[nf][0] = Bb[kk * BST + n];
                b[nf][1] = Bb[(kk + 4) * BST + n];
            }
#pragma unroll
            for (int mf = 0; mf < 4; mf++)
#pragma unroll
                for (int nf = 0; nf < 4; nf++)
                    mma_f16(acc[mf][nf], a[mf][0], a[mf][1], a[mf][2], a[mf][3],
                            b[nf][0], b[nf][1]);
        }
        s ^= 1;
    }

    if (mode == 1) {
#pragma unroll
        for (int mf = 0; mf < 4; mf++)
#pragma unroll
            for (int nf = 0; nf < 4; nf++) {
                int row  = m0 + wm + mf * 16 + g;
                int col2 = (wn + nf * 8) / 2 + c;
                Ch[(size_t)row * 64 + col2] =
                    f2h2(acc[mf][nf][0] * oscale, acc[mf][nf][1] * oscale);
                Ch[(size_t)(row + 8) * 64 + col2] =
                    f2h2(acc[mf][nf][2] * oscale, acc[mf][nf][3] * oscale);
            }
    } else {
        // V key-pair pack: rows r (g even) pair with r+1 (lane^4 holds it)
#pragma unroll
        for (int mf = 0; mf < 4; mf++)
#pragma unroll
            for (int nf = 0; nf < 4; nf++) {
                float p0 = __shfl_xor_sync(0xffffffffu, acc[mf][nf][0], 4);
                float p1 = __shfl_xor_sync(0xffffffffu, acc[mf][nf][1], 4);
                float p2 = __shfl_xor_sync(0xffffffffu, acc[mf][nf][2], 4);
                float p3 = __shfl_xor_sync(0xffffffffu, acc[mf][nf][3], 4);
                if (!(g & 1)) {
                    int r0  = m0 + wm + mf * 16 + g;
                    int col = wn + nf * 8 + 2 * c;
                    uint2 u0 = {f2h2(acc[mf][nf][0], p0), f2h2(acc[mf][nf][1], p1)};
                    *(uint2*)&g_Vp[(size_t)(r0 >> 1) * DK + col] = u0;
                    uint2 u1 = {f2h2(acc[mf][nf][2], p2), f2h2(acc[mf][nf][3], p3)};
                    *(uint2*)&g_Vp[(size_t)((r0 + 8) >> 1) * DK + col] = u1;
                }
            }
    }
}

__global__ __launch_bounds__(256) void qkv_kernel(const float* __restrict__ x)
{
    // 1/sqrt(128) * log2(e) folded into Q so softmax can use exp2
    const float scale = 0.08838834764831845f * 1.4426950408889634f;
    const unsigned* Bh = g_Wh + blockIdx.z * 65536;
    if (blockIdx.z == 0)
        qkv_gemm(x, Bh, g_Qh, scale, 1, blockIdx.x * 128);
    else if (blockIdx.z == 1)
        qkv_gemm(x, Bh, g_Kh, 1.0f, 1, blockIdx.x * 128);
    else
        qkv_gemm(x, Bh, nullptr, 1.0f, 2, blockIdx.x * 128);
}

// ---------------------------------------------------------------------------
// Output projection: out[128x128 tile] = O[8192,128] @ Wo[128,1024].
// One-shot cp.async stage, ONE barrier, 8 uninterrupted k16-slices.
// ---------------------------------------------------------------------------
#define OA_ST 68
#define OB_ST 136
#define OP_SMEM ((128*OA_ST + 64*OB_ST) * 4)   // 69,632 bytes

__global__ __launch_bounds__(256) void outproj_kernel(float* __restrict__ out)
{
    extern __shared__ __align__(16) unsigned sop[];
    unsigned* Bsm = sop + 128 * OA_ST;

    const int tid = threadIdx.x, lane = tid & 31, w = tid >> 5;
    const int wm = (w >> 2) * 64, wn = (w & 3) * 32;
    const int g = lane >> 2, c = lane & 3;
    const int m0 = blockIdx.y * 128, n0 = blockIdx.x * 128;
    const uint32_t sb = smem_u32(sop);

    {
        const int row = tid >> 1, half = tid & 1;
        const unsigned* src = &g_Oh[(size_t)(m0 + row) * 64 + half * 32];
        uint32_t dst = sb + 4u * (row * OA_ST + half * 32);
#pragma unroll
        for (int i = 0; i < 8; i++)
            cp16(dst + i * 16, src + i * 4);
    }
    {
        const int bn = (tid & 15) * 8;
#pragma unroll
        for (int it = 0; it < 4; it++) {
            const int k2 = (tid >> 4) + it * 16;
            const unsigned* src = &g_WoH[k2 * 1024 + n0 + bn];
            uint32_t dst = sb + 4u * (128 * OA_ST + k2 * OB_ST + bn);
            cp16(dst, src);
            cp16(dst + 16, src + 4);
        }
    }
    CP_COMMIT();
    CP_WAIT0();
    __syncthreads();

    float acc[4][4][4];
#pragma unroll
    for (int mf = 0; mf < 4; mf++)
#pragma unroll
        for (int nf = 0; nf < 4; nf++)
#pragma unroll
            for (int j = 0; j < 4; j++) acc[mf][nf][j] = 0.f;

    const uint32_t a_lm = sb + 4u * ((wm + (lane & 15)) * OA_ST + (lane >> 4) * 4);
#pragma unroll
    for (int ks = 0; ks < 8; ks++) {
        const int kk = ks * 8 + c;
        unsigned a[4][4], b[4][2];
#pragma unroll
        for (int mf = 0; mf < 4; mf++)
            ldmx4(a[mf], a_lm + 4u * (mf * 16 * OA_ST) + ks * 32);
#pragma unroll
        for (int nf = 0; nf < 4; nf++) {
            int n = wn + nf * 8 + g;
            b[nf][0] = Bsm[kk * OB_ST + n];
            b[nf][1] = Bsm[(kk + 4) * OB_ST + n];
        }
#pragma unroll
        for (int mf = 0; mf < 4; mf++)
#pragma unroll
            for (int nf = 0; nf < 4; nf++)
                mma_f16(acc[mf][nf], a[mf][0], a[mf][1], a[mf][2], a[mf][3],
                        b[nf][0], b[nf][1]);
    }

#pragma unroll
    for (int mf = 0; mf < 4; mf++)
#pragma unroll
        for (int nf = 0; nf < 4; nf++) {
            size_t r0 = (size_t)(m0 + wm + mf * 16 + g) * DD + n0 + wn + nf * 8 + 2 * c;
            float2 lo = {acc[mf][nf][0], acc[mf][nf][1]};
            float2 hi = {acc[mf][nf][2], acc[mf][nf][3]};
            *(float2*)&out[r0]                  = lo;
            *(float2*)&out[r0 + (size_t)8 * DD] = hi;
        }
}

// ---------------------------------------------------------------------------
// Flash attention, fp16 mma, split-KV, cp.async staging (R14 layouts).
// K fragments via ldmatrix.x4 (layout [key][d2] unchanged); V scalar LDS.
// Softmax in exp2 domain (log2e folded into Q).
// ---------------------------------------------------------------------------
#define QS2 68
#define KS2 68
#define VST 136
#define OFF_K (128*QS2)
#define OFF_V (OFF_K + 2*BKV*KS2)
#define FLASH_SMEM ((OFF_V + 2*16*VST) * 4)   // 69,632 bytes

__global__ __launch_bounds__(256, 2) void flash_kernel()
{
    extern __shared__ __align__(16) unsigned smf[];
    unsigned* Vs = smf + OFF_V;

    const int tid = threadIdx.x, lane = tid & 31, w = tid >> 5;
    const int g = lane >> 2, c = lane & 3;
    const int wm = w * 16;
    const uint32_t sbase = smem_u32(smf);
    const uint32_t qs_lm = sbase +
        4u * ((wm + (lane & 15)) * QS2 + (lane >> 4) * 4);
    // K-fragment ldmatrix lane mapping (proven in R15)
    const int lm_p = (lane >> 4) & 1;
    const int lm_h = (lane >> 3) & 1;
    const int lm_r = lane & 7;
    const uint32_t k_lm_off = 4u * ((lm_p * 8 + lm_r) * KS2 + lm_h * 4);

    const int b  = blockIdx.x / BPB;
    const int wr = BPB - 1 - (blockIdx.x % BPB);
    int qt = 0, chunk = 0, prefix = 0;
    {
        int accn = 0;
        for (int q = 0; q < 16; q++) {
            int n = (q + 2) >> 1;
            if (wr < accn + n) { qt = q; chunk = wr - accn; prefix = accn; break; }
            accn += n;
        }
    }
    const int slot = b * BPB + prefix + chunk;
    const int q0 = qt * 128;
    const int it_total = 4 * qt + 4;
    const int t0 = chunk * CHUNK;
    const int tlen = (it_total - t0 < CHUNK) ? (it_total - t0) : CHUNK;

    const size_t bT  = (size_t)b * TT;
    const size_t bT2 = (size_t)b * (TT / 2);

    const int kr = tid >> 3,  kku = (tid & 7) * 8;
    const int vk2 = tid >> 4, vn0 = (tid & 15) * 8;
    const int qr = tid >> 1,  qku = (tid & 1) * 32;

    auto stage = [&](int t, int s) {
        uint32_t kb = sbase + (OFF_K + s * BKV * KS2 + kr * KS2 + kku) * 4;
        const unsigned* ksrc = &g_Kh[(bT + (size_t)t * BKV + kr) * 64 + kku];
        cp16(kb,      ksrc);
        cp16(kb + 16, ksrc + 4);
        uint32_t vb = sbase + (OFF_V + s * 16 * VST + vk2 * VST + vn0) * 4;
        const unsigned* vsrc = &g_Vp[(bT2 + (size_t)t * 16 + vk2) * DK + vn0];
        cp16(vb,      vsrc);
        cp16(vb + 16, vsrc + 4);
    };

    {
        const unsigned* qsrc = &g_Qh[(bT + q0 + qr) * 64 + qku];
        uint32_t qb = sbase + (qr * QS2 + qku) * 4;
#pragma unroll
        for (int i = 0; i < 8; i++)
            cp16(qb + i * 16, qsrc + i * 4);
        stage(t0, 0);
        CP_COMMIT();
        CP_WAIT0();
        __syncthreads();
    }

    float mr0 = -1e30f, mr1 = -1e30f, l0 = 0.f, l1 = 0.f;
    float O[16][4];
#pragma unroll
    for (int nf = 0; nf < 16; nf++)
#pragma unroll
        for (int j = 0; j < 4; j++) O[nf][j] = 0.f;

    int s = 0;
    for (int ti = 0; ti < tlen; ti++) {
        const int t = t0 + ti;
        const uint32_t kfb = sbase + 4u * (OFF_K + s * BKV * KS2) + k_lm_off;
        unsigned* Vb = Vs + s * 16 * VST;

        if (ti + 1 < tlen) { stage(t + 1, s ^ 1); CP_COMMIT(); }

        // --- S = Q K^T : 4 n-frags, 8 k16-slices; Q+K frags via ldmatrix ---
        float sfr[4][4];
#pragma unroll
        for (int nf = 0; nf < 4; nf++)
#pragma unroll
            for (int j = 0; j < 4; j++) sfr[nf][j] = 0.f;

#pragma unroll
        for (int ks = 0; ks < 8; ks++) {
            unsigned aq[4];
            ldmx4(aq, qs_lm + ks * 32);
#pragma unroll
            for (int j = 0; j < 2; j++) {
                unsigned bk[4];
                ldmx4(bk, kfb + j * (16 * KS2 * 4) + ks * 32);
                mma_f16(sfr[2*j],   aq[0], aq[1], aq[2], aq[3], bk[0], bk[1]);
                mma_f16(sfr[2*j+1], aq[0], aq[1], aq[2], aq[3], bk[2], bk[3]);
            }
        }

        // causal mask (scale + log2e pre-folded into Q)
        if (t * BKV + BKV - 1 > q0 + wm) {
            const int r0g = q0 + wm + g, r1g = r0g + 8;
#pragma unroll
            for (int nf = 0; nf < 4; nf++) {
                int col = t * BKV + nf * 8 + 2 * c;
                if (col     > r0g) sfr[nf][0] = -1e30f;
                if (col + 1 > r0g) sfr[nf][1] = -1e30f;
                if (col     > r1g) sfr[nf][2] = -1e30f;
                if (col + 1 > r1g) sfr[nf][3] = -1e30f;
            }
        }

        // --- online softmax in exp2 domain ---
        float rm0 = -1e30f, rm1 = -1e30f;
#pragma unroll
        for (int nf = 0; nf < 4; nf++) {
            rm0 = fmaxf(rm0, fmaxf(sfr[nf][0], sfr[nf][1]));
            rm1 = fmaxf(rm1, fmaxf(sfr[nf][2], sfr[nf][3]));
        }
        rm0 = fmaxf(rm0, __shfl_xor_sync(0xffffffffu, rm0, 1));
        rm0 = fmaxf(rm0, __shfl_xor_sync(0xffffffffu, rm0, 2));
        rm1 = fmaxf(rm1, __shfl_xor_sync(0xffffffffu, rm1, 1));
        rm1 = fmaxf(rm1, __shfl_xor_sync(0xffffffffu, rm1, 2));

        float mn0 = fmaxf(mr0, rm0), mn1 = fmaxf(mr1, rm1);
        float al0 = exp2f(mr0 - mn0), al1 = exp2f(mr1 - mn1);
        float sum0 = 0.f, sum1 = 0.f;
#pragma unroll
        for (int nf = 0; nf < 4; nf++) {
            sfr[nf][0] = exp2f(sfr[nf][0] - mn0);
            sfr[nf][1] = exp2f(sfr[nf][1] - mn0);
            sfr[nf][2] = exp2f(sfr[nf][2] - mn1);
            sfr[nf][3] = exp2f(sfr[nf][3] - mn1);
            sum0 += sfr[nf][0] + sfr[nf][1];
            sum1 += sfr[nf][2] + sfr[nf][3];
        }
        sum0 += __shfl_xor_sync(0xffffffffu, sum0, 1);
        sum0 += __shfl_xor_sync(0xffffffffu, sum0, 2);
        sum1 += __shfl_xor_sync(0xffffffffu, sum1, 1);
        sum1 += __shfl_xor_sync(0xffffffffu, sum1, 2);

        l0 = l0 * al0 + sum0; l1 = l1 * al1 + sum1;
        mr0 = mn0; mr1 = mn1;
#pragma unroll
        for (int nf = 0; nf < 16; nf++) {
            O[nf][0] *= al0; O[nf][1] *= al0;
            O[nf][2] *= al1; O[nf][3] *= al1;
        }

        // --- O += P V : S-frags pack directly into PV A-frags ---
#pragma unroll
        for (int ksl = 0; ksl < 2; ksl++) {
            unsigned a0 = f2h2(sfr[2 * ksl][0],     sfr[2 * ksl][1]);
            unsigned a1 = f2h2(sfr[2 * ksl][2],     sfr[2 * ksl][3]);
            unsigned a2 = f2h2(sfr[2 * ksl + 1][0], sfr[2 * ksl + 1][1]);
            unsigned a3 = f2h2(sfr[2 * ksl + 1][2], sfr[2 * ksl + 1][3]);
            const int kk = ksl * 8 + c;
#pragma unroll
            for (int nf = 0; nf < 16; nf++) {
                int n = nf * 8 + g;
                mma_f16(O[nf], a0, a1, a2, a3,
                        Vb[kk * VST + n], Vb[(kk + 4) * VST + n]);
            }
        }

        if (ti + 1 < tlen) CP_WAIT0();
        __syncthreads();
        s ^= 1;
    }

    unsigned* pO = g_pOh + (size_t)slot * 128 * 64;
#pragma unroll
    for (int nf = 0; nf < 16; nf++) {
        int col2 = nf * 4 + c;
        pO[(wm + g) * 64 + col2]     = f2h2(O[nf][0], O[nf][1]);
        pO[(wm + g + 8) * 64 + col2] = f2h2(O[nf][2], O[nf][3]);
    }
    if (c == 0) {
        float* ml = g_pml + slot * 256;
        ml[(wm + g) * 2]         = mr0;
        ml[(wm + g) * 2 + 1]     = l0;
        ml[(wm + g + 8) * 2]     = mr1;
        ml[(wm + g + 8) * 2 + 1] = l1;
    }
}

// ---------------------------------------------------------------------------
// Combine partial chunks -> g_Oh (normalized, packed fp16). 1024 blocks.
// m values are in log2 units -> exp2f weights.
// ---------------------------------------------------------------------------
__global__ __launch_bounds__(256) void combine_kernel()
{
    const int idx  = blockIdx.x * 256 + threadIdx.x;
    const int col2 = (idx & 31) * 2;
    const int row  = (idx >> 5) & 127;
    const int bqt  = idx >> 12;
    const int b = bqt >> 4, qt = bqt & 15;
    const int nch = (qt + 2) >> 1;
    int prefix = 0;
#pragma unroll
    for (int q = 0; q < 16; q++)
        if (q < qt) prefix += (q + 2) >> 1;
    const int base = b * BPB + prefix;

    float M = -1e30f;
    for (int i = 0; i < nch; i++)
        M = fmaxf(M, g_pml[(base + i) * 256 + row * 2]);

    float L = 0.f;
    float4 a = {0.f, 0.f, 0.f, 0.f};
    for (int i = 0; i < nch; i++) {
        float mi = g_pml[(base + i) * 256 + row * 2];
        float li = g_pml[(base + i) * 256 + row * 2 + 1];
        float wgt = exp2f(mi - M);
        L += wgt * li;
        uint2 v = *(const uint2*)&g_pOh[((size_t)(base + i) * 128 + row) * 64 + col2];
        float2 lo = h2f2(v.x), hi = h2f2(v.y);
        a.x += wgt * lo.x; a.y += wgt * lo.y;
        a.z += wgt * hi.x; a.w += wgt * hi.y;
    }
    const float invL = 1.f / L;
    const size_t orow = (size_t)b * TT + qt * 128 + row;
    g_Oh[orow * 64 + col2]     = f2h2(a.x * invL, a.y * invL);
    g_Oh[orow * 64 + col2 + 1] = f2h2(a.z * invL, a.w * invL);
}

// ---------------------------------------------------------------------------
extern "C" void kernel_launch(void* const* d_in, const int* in_sizes, int n_in,
                              void* d_out, int out_size)
{
    const float* x  = (const float*)d_in[0];
    const float* Wq = (const float*)d_in[1];
    const float* Wk = (const float*)d_in[2];
    const float* Wv = (const float*)d_in[3];
    const float* Wo = (const float*)d_in[4];
    float* out = (float*)d_out;

    cudaFuncSetAttribute(flash_kernel,
                         cudaFuncAttributeMaxDynamicSharedMemorySize, FLASH_SMEM);
    cudaFuncSetAttribute(outproj_kernel,
                         cudaFuncAttributeMaxDynamicSharedMemorySize, OP_SMEM);

    // Pack all weights into fp16 k-pair layout
    packw_kernel<<<1024, 256>>>(Wq, Wk, Wv, Wo);

    // QKV projections: A = fp32 x (cvt), B = packed weights via cp.async
    qkv_kernel<<<dim3(RR / 128, 1, 3), 256>>>(x);

    // Split-KV causal flash attention (288 blocks = full wave at 2/SM)
    flash_kernel<<<NSLOT, 256, FLASH_SMEM>>>();

    // Merge partial softmax chunks -> packed fp16 O
    combine_kernel<<<RR * 32 / 256, 256>>>();

    // Output projection: one-shot smem, no mainloop barriers
    outproj_kernel<<<dim3(DD / 128, RR / 128), 256, OP_SMEM>>>(out);
}